// round 1
// baseline (speedup 1.0000x reference)
#include <cuda_runtime.h>
#include <cuda_bf16.h>
#include <math.h>

#define DIMS 256
#define KCODES 1024
#define BM 128
#define BN 64
#define BK 8
#define TM 8
#define TN 4
#define NTHREADS 256

__device__ float d_cnorm[KCODES];
__device__ float d_counts[KCODES];

// ---------------------------------------------------------------------------
// prep: zero histogram, compute ||c||^2 per code. 1024 warps total.
// ---------------------------------------------------------------------------
__global__ void prep_kernel(const float* __restrict__ cb) {
    int gtid = blockIdx.x * blockDim.x + threadIdx.x;
    if (gtid < KCODES) d_counts[gtid] = 0.0f;
    int w = gtid >> 5;          // global warp id = code id (0..1023)
    int lane = threadIdx.x & 31;
    if (w < KCODES) {
        const float* r = cb + (size_t)w * DIMS;
        float s = 0.0f;
        #pragma unroll
        for (int i = 0; i < DIMS / 32; i++) {
            float v = r[lane + i * 32];
            s = fmaf(v, v, s);
        }
        #pragma unroll
        for (int off = 16; off > 0; off >>= 1)
            s += __shfl_xor_sync(0xFFFFFFFFu, s, off);
        if (lane == 0) d_cnorm[w] = s;
    }
}

// ---------------------------------------------------------------------------
// main: tiled distance GEMM + fused argmin + gather + histogram
// grid.x = nrows/BM, 256 threads
// ---------------------------------------------------------------------------
__global__ __launch_bounds__(NTHREADS, 2)
void vq_kernel(const float* __restrict__ z, const float* __restrict__ cb,
               float* __restrict__ out) {
    __shared__ float As[BK][BM];   // 4 KB, [k][row]
    __shared__ float Bs[BK][BN];   // 2 KB, [k][code]
    __shared__ float redV[BM][16]; // 8 KB
    __shared__ int   redI[BM][16]; // 8 KB
    __shared__ int   sIdx[BM];

    const int tid = threadIdx.x;
    const int tc = tid & 15;       // code-dir thread 0..15
    const int tr = tid >> 4;       // row-dir thread 0..15
    const int rowBase = blockIdx.x * BM;

    // A-load assignment: each thread loads one float4 per k-chunk
    const int aRow = tid >> 1;          // 0..127
    const int aQuad = (tid & 1) * 4;    // 0 or 4
    // B-load assignment: threads 0..127 load one float4 each
    const int bCode = tid >> 1;         // 0..63 (valid when tid<128)
    const int bQuad = (tid & 1) * 4;

    float best[TM];
    int bidx[TM];
    #pragma unroll
    for (int i = 0; i < TM; i++) { best[i] = 3.4e38f; bidx[i] = 0; }

    const float* zRowPtr = z + (size_t)(rowBase + aRow) * DIMS + aQuad;

    for (int cchunk = 0; cchunk < KCODES; cchunk += BN) {
        float acc[TM][TN];
        #pragma unroll
        for (int i = 0; i < TM; i++)
            #pragma unroll
            for (int j = 0; j < TN; j++) acc[i][j] = 0.0f;

        const float* cbPtr = cb + (size_t)(cchunk + bCode) * DIMS + bQuad;

        for (int dk = 0; dk < DIMS; dk += BK) {
            float4 av = *(const float4*)(zRowPtr + dk);
            float4 bv = make_float4(0.f, 0.f, 0.f, 0.f);
            if (tid < 128) bv = *(const float4*)(cbPtr + dk);

            __syncthreads();   // previous compute done before overwrite
            As[aQuad + 0][aRow] = av.x;
            As[aQuad + 1][aRow] = av.y;
            As[aQuad + 2][aRow] = av.z;
            As[aQuad + 3][aRow] = av.w;
            if (tid < 128) {
                Bs[bQuad + 0][bCode] = bv.x;
                Bs[bQuad + 1][bCode] = bv.y;
                Bs[bQuad + 2][bCode] = bv.z;
                Bs[bQuad + 3][bCode] = bv.w;
            }
            __syncthreads();

            #pragma unroll
            for (int k = 0; k < BK; k++) {
                float a[TM], b[TN];
                *(float4*)(a)     = *(const float4*)&As[k][tr * TM];
                *(float4*)(a + 4) = *(const float4*)&As[k][tr * TM + 4];
                *(float4*)(b)     = *(const float4*)&Bs[k][tc * TN];
                #pragma unroll
                for (int i = 0; i < TM; i++)
                    #pragma unroll
                    for (int j = 0; j < TN; j++)
                        acc[i][j] = fmaf(a[i], b[j], acc[i][j]);
            }
        }

        // fold chunk into running argmin: cost = ||c||^2 - 2 * dot
        #pragma unroll
        for (int j = 0; j < TN; j++) {
            int code = cchunk + tc * TN + j;
            float cn = __ldg(&d_cnorm[code]);
            #pragma unroll
            for (int i = 0; i < TM; i++) {
                float cost = fmaf(-2.0f, acc[i][j], cn);
                if (cost < best[i]) { best[i] = cost; bidx[i] = code; }
            }
        }
    }

    // cross-thread argmin reduction (16 candidates per row)
    #pragma unroll
    for (int i = 0; i < TM; i++) {
        redV[tr * TM + i][tc] = best[i];
        redI[tr * TM + i][tc] = bidx[i];
    }
    __syncthreads();

    if (tid < BM) {
        float bv = 3.4e38f;
        int bi = 0x7FFFFFFF;
        #pragma unroll
        for (int t = 0; t < 16; t++) {
            float v = redV[tid][t];
            int ix = redI[tid][t];
            if (v < bv || (v == bv && ix < bi)) { bv = v; bi = ix; }
        }
        sIdx[tid] = bi;
        atomicAdd(&d_counts[bi], 1.0f);
    }
    __syncthreads();

    // gather: z_q[row] = codebook[idx[row]]
    const float4* cb4 = (const float4*)cb;
    float4* out4 = (float4*)out;
    const int Q = DIMS / 4;  // 64 float4 per row
    for (int idx = tid; idx < BM * Q; idx += NTHREADS) {
        int r = idx >> 6;
        int q = idx & 63;
        int code = sIdx[r];
        out4[(size_t)(rowBase + r) * Q + q] = cb4[(size_t)code * Q + q];
    }
}

// ---------------------------------------------------------------------------
// epilogue: loss + perplexity
// ---------------------------------------------------------------------------
__global__ void perp_kernel(float* __restrict__ out, int nd, float n) {
    __shared__ float s[KCODES];
    int t = threadIdx.x;
    float e = d_counts[t] / n;
    s[t] = e * logf(e + 1e-10f);
    __syncthreads();
    for (int st = KCODES / 2; st > 0; st >>= 1) {
        if (t < st) s[t] += s[t + st];
        __syncthreads();
    }
    if (t == 0) {
        out[nd] = 0.0f;                 // loss (eval mode)
        out[nd + 1] = expf(-s[0]);      // perplexity
    }
}

extern "C" void kernel_launch(void* const* d_in, const int* in_sizes, int n_in,
                              void* d_out, int out_size) {
    const float* z = (const float*)d_in[0];
    const float* cb = (const float*)d_in[1];
    float* out = (float*)d_out;

    int nrows = in_sizes[0] / DIMS;   // 65536
    prep_kernel<<<128, 256>>>(cb);
    vq_kernel<<<nrows / BM, NTHREADS>>>(z, cb, out);
    long nd = (long)nrows * DIMS;
    if ((long)out_size >= nd + 2)
        perp_kernel<<<1, KCODES>>>(out, (int)nd, (float)nrows);
}

// round 3
// speedup vs baseline: 1.1121x; 1.1121x over previous
#include <cuda_runtime.h>
#include <cuda_bf16.h>
#include <math.h>

#define DIMS 256
#define KCODES 1024
#define BM 128
#define BN 128
#define BK 16
#define NTHREADS 256

typedef unsigned long long u64;

__device__ __forceinline__ u64 pack2(float lo, float hi) {
    u64 r; asm("mov.b64 %0, {%1, %2};" : "=l"(r) : "f"(lo), "f"(hi)); return r;
}
__device__ __forceinline__ void unpack2(u64 v, float& lo, float& hi) {
    asm("mov.b64 {%0, %1}, %2;" : "=f"(lo), "=f"(hi) : "l"(v));
}
__device__ __forceinline__ u64 fma2(u64 a, u64 b, u64 c) {
    u64 d; asm("fma.rn.f32x2 %0, %1, %2, %3;" : "=l"(d) : "l"(a), "l"(b), "l"(c)); return d;
}

__device__ float d_cnorm[KCODES];
__device__ float d_counts[KCODES];

// ---------------------------------------------------------------------------
// prep: zero histogram, compute ||c||^2 per code
// ---------------------------------------------------------------------------
__global__ void prep_kernel(const float* __restrict__ cb) {
    int gtid = blockIdx.x * blockDim.x + threadIdx.x;
    if (gtid < KCODES) d_counts[gtid] = 0.0f;
    int w = gtid >> 5;
    int lane = threadIdx.x & 31;
    if (w < KCODES) {
        const float* r = cb + (size_t)w * DIMS;
        float s = 0.0f;
        #pragma unroll
        for (int i = 0; i < DIMS / 32; i++) {
            float v = r[lane + i * 32];
            s = fmaf(v, v, s);
        }
        #pragma unroll
        for (int off = 16; off > 0; off >>= 1)
            s += __shfl_xor_sync(0xFFFFFFFFu, s, off);
        if (lane == 0) d_cnorm[w] = s;
    }
}

// ---------------------------------------------------------------------------
// main: FFMA2 tiled distance GEMM + fused argmin + gather + histogram
// ---------------------------------------------------------------------------
__global__ __launch_bounds__(NTHREADS, 2)
void vq_kernel(const float* __restrict__ z, const float* __restrict__ cb,
               float* __restrict__ out) {
    __shared__ float As[BK][BM];    // 8 KB  [k][row]
    __shared__ float Bs[BK][BN];    // 8 KB  [k][code]
    __shared__ float redV[BM][16];  // 8 KB
    __shared__ int   redI[BM][16];  // 8 KB
    __shared__ int   sIdx[BM];

    const int tid = threadIdx.x;
    const int tc = tid & 15;        // code-dir 0..15   -> codes tc*8..+7
    const int tr = tid >> 4;        // row-dir  0..15   -> rows  tr*8..+7
    const int rowBase = blockIdx.x * BM;

    // load assignments: each thread moves 2 float4 of A and 2 of B per step
    const int ldRow = tid >> 1;            // 0..127
    const int ldQ = (tid & 1) * 4;         // 0 or 4  (second at +8)

    float best[8];
    int bidx[8];
    #pragma unroll
    for (int i = 0; i < 8; i++) { best[i] = 3.4e38f; bidx[i] = 0; }

    const float* zRowPtr = z + (size_t)(rowBase + ldRow) * DIMS + ldQ;

    for (int cchunk = 0; cchunk < KCODES; cchunk += BN) {
        u64 acc[4][8];   // [row-pair][col]
        #pragma unroll
        for (int m = 0; m < 4; m++)
            #pragma unroll
            for (int j = 0; j < 8; j++) acc[m][j] = 0ULL;

        const float* cbPtr = cb + (size_t)(cchunk + ldRow) * DIMS + ldQ;

        for (int dk = 0; dk < DIMS; dk += BK) {
            float4 av0 = *(const float4*)(zRowPtr + dk);
            float4 av1 = *(const float4*)(zRowPtr + dk + 8);
            float4 bv0 = *(const float4*)(cbPtr + dk);
            float4 bv1 = *(const float4*)(cbPtr + dk + 8);

            __syncthreads();
            As[ldQ + 0][ldRow] = av0.x;
            As[ldQ + 1][ldRow] = av0.y;
            As[ldQ + 2][ldRow] = av0.z;
            As[ldQ + 3][ldRow] = av0.w;
            As[ldQ + 8][ldRow] = av1.x;
            As[ldQ + 9][ldRow] = av1.y;
            As[ldQ + 10][ldRow] = av1.z;
            As[ldQ + 11][ldRow] = av1.w;
            Bs[ldQ + 0][ldRow] = bv0.x;
            Bs[ldQ + 1][ldRow] = bv0.y;
            Bs[ldQ + 2][ldRow] = bv0.z;
            Bs[ldQ + 3][ldRow] = bv0.w;
            Bs[ldQ + 8][ldRow] = bv1.x;
            Bs[ldQ + 9][ldRow] = bv1.y;
            Bs[ldQ + 10][ldRow] = bv1.z;
            Bs[ldQ + 11][ldRow] = bv1.w;
            __syncthreads();

            #pragma unroll
            for (int k = 0; k < BK; k++) {
                ulonglong2 aa0 = *(const ulonglong2*)&As[k][tr * 8];
                ulonglong2 aa1 = *(const ulonglong2*)&As[k][tr * 8 + 4];
                u64 ap[4] = { aa0.x, aa0.y, aa1.x, aa1.y };

                float4 b0 = *(const float4*)&Bs[k][tc * 8];
                float4 b1 = *(const float4*)&Bs[k][tc * 8 + 4];
                u64 bb[8];
                bb[0] = pack2(b0.x, b0.x);
                bb[1] = pack2(b0.y, b0.y);
                bb[2] = pack2(b0.z, b0.z);
                bb[3] = pack2(b0.w, b0.w);
                bb[4] = pack2(b1.x, b1.x);
                bb[5] = pack2(b1.y, b1.y);
                bb[6] = pack2(b1.z, b1.z);
                bb[7] = pack2(b1.w, b1.w);

                #pragma unroll
                for (int j = 0; j < 8; j++)
                    #pragma unroll
                    for (int m = 0; m < 4; m++)
                        acc[m][j] = fma2(ap[m], bb[j], acc[m][j]);
            }
        }

        // fold chunk into running argmin: cost = ||c||^2 - 2*dot
        #pragma unroll
        for (int j = 0; j < 8; j++) {
            int code = cchunk + tc * 8 + j;
            float cn = __ldg(&d_cnorm[code]);
            #pragma unroll
            for (int m = 0; m < 4; m++) {
                float d0, d1;
                unpack2(acc[m][j], d0, d1);
                float c0 = fmaf(-2.0f, d0, cn);
                float c1 = fmaf(-2.0f, d1, cn);
                if (c0 < best[2 * m])     { best[2 * m] = c0;     bidx[2 * m] = code; }
                if (c1 < best[2 * m + 1]) { best[2 * m + 1] = c1; bidx[2 * m + 1] = code; }
            }
        }
    }

    // cross-thread argmin reduction (16 candidates per row)
    __syncthreads();
    #pragma unroll
    for (int i = 0; i < 8; i++) {
        redV[tr * 8 + i][tc] = best[i];
        redI[tr * 8 + i][tc] = bidx[i];
    }
    __syncthreads();

    if (tid < BM) {
        float bv = 3.4e38f;
        int bi = 0x7FFFFFFF;
        #pragma unroll
        for (int t = 0; t < 16; t++) {
            float v = redV[tid][t];
            int ix = redI[tid][t];
            if (v < bv || (v == bv && ix < bi)) { bv = v; bi = ix; }
        }
        sIdx[tid] = bi;
        atomicAdd(&d_counts[bi], 1.0f);
    }
    __syncthreads();

    // gather: z_q[row] = codebook[idx[row]]
    const float4* cb4 = (const float4*)cb;
    float4* out4 = (float4*)out;
    const int Q = DIMS / 4;  // 64
    for (int idx = tid; idx < BM * Q; idx += NTHREADS) {
        int r = idx >> 6;
        int q = idx & 63;
        int code = sIdx[r];
        out4[(size_t)(rowBase + r) * Q + q] = cb4[(size_t)code * Q + q];
    }
}

// ---------------------------------------------------------------------------
// epilogue: loss + perplexity
// ---------------------------------------------------------------------------
__global__ void perp_kernel(float* __restrict__ out, int nd, float n) {
    __shared__ float s[KCODES];
    int t = threadIdx.x;
    float e = d_counts[t] / n;
    s[t] = e * logf(e + 1e-10f);
    __syncthreads();
    for (int st = KCODES / 2; st > 0; st >>= 1) {
        if (t < st) s[t] += s[t + st];
        __syncthreads();
    }
    if (t == 0) {
        out[nd] = 0.0f;
        out[nd + 1] = expf(-s[0]);
    }
}

extern "C" void kernel_launch(void* const* d_in, const int* in_sizes, int n_in,
                              void* d_out, int out_size) {
    const float* z = (const float*)d_in[0];
    const float* cb = (const float*)d_in[1];
    float* out = (float*)d_out;

    int nrows = in_sizes[0] / DIMS;   // 65536
    prep_kernel<<<128, 256>>>(cb);
    vq_kernel<<<nrows / BM, NTHREADS>>>(z, cb, out);
    long nd = (long)nrows * DIMS;
    if ((long)out_size >= nd + 2)
        perp_kernel<<<1, KCODES>>>(out, (int)nd, (float)nrows);
}

// round 4
// speedup vs baseline: 1.2508x; 1.1248x over previous
#include <cuda_runtime.h>
#include <cuda_bf16.h>
#include <math.h>

#define DIMS 256
#define KCODES 1024
#define NROWS_MAX 65536

#define BM 128
#define BN 64
#define NTHREADS 256
#define A_STRIDE 520              // bf16 units per A smem row (512 data + 8 pad)
#define B_STRIDE 72               // bf16 units per B smem row (64 data + 8 pad)
#define B_BUF (BN * B_STRIDE)     // one B buffer in bf16 units
#define A_BYTES (BM * A_STRIDE * 2)
#define SMEM_TOTAL (A_BYTES + 2 * B_BUF * 2)
#define MARGIN 0.125f

__device__ float d_cnorm[KCODES];
__device__ float d_counts[KCODES];
__device__ __nv_bfloat16 d_cbs[KCODES * 512];  // [code][ ch(0..255) | cl(256..511) ]
__device__ int d_idx[NROWS_MAX];
__device__ int d_flagList[NROWS_MAX];
__device__ int d_flagCount;

// ---------------------------------------------------------------------------
// prep: zero counts/flags, compute ||c||^2, split codebook to bf16 hi/lo
// ---------------------------------------------------------------------------
__global__ void prep_kernel(const float* __restrict__ cb) {
    int gtid = blockIdx.x * blockDim.x + threadIdx.x;
    if (gtid < KCODES) d_counts[gtid] = 0.0f;
    if (gtid == 0) d_flagCount = 0;
    int w = gtid >> 5;
    int lane = threadIdx.x & 31;
    if (w < KCODES) {
        const float* r = cb + (size_t)w * DIMS;
        float s = 0.0f;
        #pragma unroll
        for (int i = 0; i < DIMS / 32; i++) {
            int d = lane + i * 32;
            float v = r[d];
            s = fmaf(v, v, s);
            __nv_bfloat16 h = __float2bfloat16(v);
            __nv_bfloat16 l = __float2bfloat16(v - __bfloat162float(h));
            d_cbs[(size_t)w * 512 + d] = h;
            d_cbs[(size_t)w * 512 + 256 + d] = l;
        }
        #pragma unroll
        for (int off = 16; off > 0; off >>= 1)
            s += __shfl_xor_sync(0xFFFFFFFFu, s, off);
        if (lane == 0) d_cnorm[w] = s;
    }
}

// ---------------------------------------------------------------------------
// main: bf16-split HMMA distance GEMM + top-2 argmin + flag + gather
// ---------------------------------------------------------------------------
__device__ __forceinline__ void mma_bf16(float* c, const unsigned* a,
                                         unsigned b0, unsigned b1) {
    asm volatile(
        "mma.sync.aligned.m16n8k16.row.col.f32.bf16.bf16.f32 "
        "{%0,%1,%2,%3}, {%4,%5,%6,%7}, {%8,%9}, {%0,%1,%2,%3};"
        : "+f"(c[0]), "+f"(c[1]), "+f"(c[2]), "+f"(c[3])
        : "r"(a[0]), "r"(a[1]), "r"(a[2]), "r"(a[3]), "r"(b0), "r"(b1));
}

__global__ void vq_kernel(const float* __restrict__ z,
                          const float* __restrict__ cb,
                          float* __restrict__ out) {
    extern __shared__ char smem[];
    __nv_bfloat16* As = (__nv_bfloat16*)smem;
    __nv_bfloat16* Bs = (__nv_bfloat16*)(smem + A_BYTES);
    // reduction region aliases the B buffers (used only after GEMM done)
    float* redB1 = (float*)(smem + A_BYTES);
    float* redB2 = redB1 + BM * 8;
    int*   redI  = (int*)(redB2 + BM * 8);
    int*   sIdx  = redI + BM * 8;

    const int tid = threadIdx.x;
    const int lane = tid & 31;
    const int wid = tid >> 5;
    const int g = lane >> 2;        // 0..7
    const int tig = lane & 3;       // 0..3
    const int warpRow = wid & 3;    // 4 row-warps (32 rows each)
    const int warpCol = wid >> 2;   // 2 col-warps (32 cols each)
    const int rowBase = blockIdx.x * BM;

    // ---- fill A: split z rows into bf16 hi|lo, resident for whole kernel ----
    for (int i = tid; i < BM * DIMS; i += NTHREADS) {
        int r = i >> 8, d = i & 255;
        float v = z[(size_t)(rowBase + r) * DIMS + d];
        __nv_bfloat16 h = __float2bfloat16(v);
        __nv_bfloat16 l = __float2bfloat16(v - __bfloat162float(h));
        As[r * A_STRIDE + d] = h;
        As[r * A_STRIDE + 256 + d] = l;
    }
    __syncthreads();

    float best1[4], best2[4];
    int idx1[4];
    #pragma unroll
    for (int i = 0; i < 4; i++) { best1[i] = 3.4e38f; best2[i] = 3.4e38f; idx1[i] = 0; }

    // B tile loader assignment
    const int bRow = tid >> 2;      // 0..63
    const int bPart = (tid & 3) * 16;

    for (int chnk = 0; chnk < KCODES / BN; chnk++) {
        float acc[2][4][4];
        #pragma unroll
        for (int mf = 0; mf < 2; mf++)
            #pragma unroll
            for (int nf = 0; nf < 4; nf++)
                #pragma unroll
                for (int q = 0; q < 4; q++) acc[mf][nf][q] = 0.0f;

        const __nv_bfloat16* gB = d_cbs + (size_t)(chnk * BN + bRow) * 512 + bPart;

        // 12 k-steps: s -> seg = s>>2 (A,B half selection), ks = s&3 (k offset)
        // seg 0: A=zh(0) B=ch(0); seg 1: A=zh(0) B=cl(256); seg 2: A=zl(256) B=ch(0)
        uint4 p0, p1;
        {   // preload step 0 -> buf 0
            p0 = *(const uint4*)(gB + 0);
            p1 = *(const uint4*)(gB + 8);
            __nv_bfloat16* dst = Bs + bRow * B_STRIDE + bPart;
            *(uint4*)dst = p0;
            *(uint4*)(dst + 8) = p1;
        }
        __syncthreads();

        #pragma unroll
        for (int s = 0; s < 12; s++) {
            const int seg = s >> 2;
            const int ks = s & 3;
            // prefetch next step
            if (s + 1 < 12) {
                int nseg = (s + 1) >> 2;
                int nks = (s + 1) & 3;
                int bOff = (nseg == 1 ? 256 : 0) + nks * 64;
                p0 = *(const uint4*)(gB + bOff);
                p1 = *(const uint4*)(gB + bOff + 8);
            }
            // compute current step from buf s&1
            {
                const int aK = (seg == 2 ? 256 : 0) + ks * 64;
                const __nv_bfloat16* Ab = As + (warpRow * 32) * A_STRIDE + aK;
                const __nv_bfloat16* Bb = Bs + (s & 1) * B_BUF + (warpCol * 32) * B_STRIDE;
                #pragma unroll
                for (int kk = 0; kk < 4; kk++) {
                    const int kloc = kk * 16 + tig * 2;
                    unsigned a[2][4];
                    #pragma unroll
                    for (int mf = 0; mf < 2; mf++) {
                        const __nv_bfloat16* ap = Ab + (mf * 16 + g) * A_STRIDE + kloc;
                        a[mf][0] = *(const unsigned*)(ap);
                        a[mf][1] = *(const unsigned*)(ap + 8 * A_STRIDE);
                        a[mf][2] = *(const unsigned*)(ap + 8);
                        a[mf][3] = *(const unsigned*)(ap + 8 * A_STRIDE + 8);
                    }
                    #pragma unroll
                    for (int nf = 0; nf < 4; nf++) {
                        const __nv_bfloat16* bp = Bb + (nf * 8 + g) * B_STRIDE + kloc;
                        unsigned b0 = *(const unsigned*)(bp);
                        unsigned b1 = *(const unsigned*)(bp + 8);
                        #pragma unroll
                        for (int mf = 0; mf < 2; mf++)
                            mma_bf16(acc[mf][nf], a[mf], b0, b1);
                    }
                }
            }
            // store prefetched into other buffer
            if (s + 1 < 12) {
                __nv_bfloat16* dst = Bs + ((s + 1) & 1) * B_BUF + bRow * B_STRIDE + bPart;
                *(uint4*)dst = p0;
                *(uint4*)(dst + 8) = p1;
            }
            __syncthreads();
        }

        // fold chunk into per-row top-2:  cost = ||c||^2 - 2*dot
        #pragma unroll
        for (int nf = 0; nf < 4; nf++) {
            #pragma unroll
            for (int cc = 0; cc < 2; cc++) {
                int col = chnk * BN + warpCol * 32 + nf * 8 + tig * 2 + cc;
                float cn = __ldg(&d_cnorm[col]);
                #pragma unroll
                for (int mf = 0; mf < 2; mf++) {
                    #pragma unroll
                    for (int sub = 0; sub < 2; sub++) {
                        float cost = fmaf(-2.0f, acc[mf][nf][sub * 2 + cc], cn);
                        int rr = mf * 2 + sub;
                        if (cost < best1[rr]) {
                            best2[rr] = best1[rr];
                            best1[rr] = cost;
                            idx1[rr] = col;
                        } else if (cost < best2[rr]) {
                            best2[rr] = cost;
                        }
                    }
                }
            }
        }
    }

    __syncthreads();  // GEMM fully done; reuse B region for reduction

    const int slot = warpCol * 4 + tig;  // 8 slots per row
    #pragma unroll
    for (int rr = 0; rr < 4; rr++) {
        int r = warpRow * 32 + (rr >> 1) * 16 + (rr & 1) * 8 + g;
        redB1[r * 8 + slot] = best1[rr];
        redB2[r * 8 + slot] = best2[rr];
        redI[r * 8 + slot] = idx1[rr];
    }
    __syncthreads();

    if (tid < BM) {
        float b1 = 3.4e38f, b2 = 3.4e38f;
        int i1 = 0x7FFFFFFF;
        #pragma unroll
        for (int t = 0; t < 8; t++) {
            float v1 = redB1[tid * 8 + t];
            float v2 = redB2[tid * 8 + t];
            int ix = redI[tid * 8 + t];
            if (v1 < b1) {
                b2 = fminf(b1, v2);
                b1 = v1; i1 = ix;
            } else if (v1 == b1) {
                i1 = min(i1, ix);
                b2 = fminf(b2, v2);
            } else {
                b2 = fminf(b2, v1);
            }
        }
        d_idx[rowBase + tid] = i1;
        sIdx[tid] = i1;
        if (b2 - b1 < MARGIN) {
            int p = atomicAdd(&d_flagCount, 1);
            d_flagList[p] = rowBase + tid;
        }
    }
    __syncthreads();

    // gather z_q rows (flagged rows may be rewritten by rescan)
    const float4* cb4 = (const float4*)cb;
    float4* out4 = (float4*)out;
    for (int i = tid; i < BM * 64; i += NTHREADS) {
        int r = i >> 6, q = i & 63;
        int code = sIdx[r];
        out4[(size_t)(rowBase + r) * 64 + q] = cb4[(size_t)code * 64 + q];
    }
}

// ---------------------------------------------------------------------------
// rescan: exact fp32 full scan for ambiguous rows
// ---------------------------------------------------------------------------
__global__ void rescan_kernel(const float* __restrict__ z,
                              const float* __restrict__ cb,
                              float* __restrict__ out) {
    __shared__ float zr[DIMS];
    __shared__ float rv[256];
    __shared__ int ri[256];
    const int tid = threadIdx.x;
    const int cnt = d_flagCount;

    for (int it = blockIdx.x; it < cnt; it += gridDim.x) {
        int row = d_flagList[it];
        zr[tid] = z[(size_t)row * DIMS + tid];
        __syncthreads();

        float b = 3.4e38f;
        int bi = 0x7FFFFFFF;
        #pragma unroll
        for (int cc = 0; cc < KCODES / 256; cc++) {
            int c = tid + cc * 256;
            const float4* cp = (const float4*)(cb + (size_t)c * DIMS);
            float dot = 0.0f;
            #pragma unroll 16
            for (int q = 0; q < 64; q++) {
                float4 cv = cp[q];
                dot = fmaf(zr[q * 4 + 0], cv.x, dot);
                dot = fmaf(zr[q * 4 + 1], cv.y, dot);
                dot = fmaf(zr[q * 4 + 2], cv.z, dot);
                dot = fmaf(zr[q * 4 + 3], cv.w, dot);
            }
            float cost = fmaf(-2.0f, dot, __ldg(&d_cnorm[c]));
            if (cost < b || (cost == b && c < bi)) { b = cost; bi = c; }
        }
        rv[tid] = b; ri[tid] = bi;
        __syncthreads();
        for (int st = 128; st > 0; st >>= 1) {
            if (tid < st) {
                float v = rv[tid + st];
                int ix = ri[tid + st];
                if (v < rv[tid] || (v == rv[tid] && ix < ri[tid])) {
                    rv[tid] = v; ri[tid] = ix;
                }
            }
            __syncthreads();
        }
        int w = ri[0];
        if (tid == 0) d_idx[row] = w;
        out[(size_t)row * DIMS + tid] = cb[(size_t)w * DIMS + tid];
        __syncthreads();
    }
}

// ---------------------------------------------------------------------------
// histogram from final indices, then perplexity
// ---------------------------------------------------------------------------
__global__ void hist_kernel(int nrows) {
    int i = blockIdx.x * blockDim.x + threadIdx.x;
    if (i < nrows) atomicAdd(&d_counts[d_idx[i]], 1.0f);
}

__global__ void perp_kernel(float* __restrict__ out, int nd, float n) {
    __shared__ float s[KCODES];
    int t = threadIdx.x;
    float e = d_counts[t] / n;
    s[t] = e * logf(e + 1e-10f);
    __syncthreads();
    for (int st = KCODES / 2; st > 0; st >>= 1) {
        if (t < st) s[t] += s[t + st];
        __syncthreads();
    }
    if (t == 0) {
        out[nd] = 0.0f;
        out[nd + 1] = expf(-s[0]);
    }
}

extern "C" void kernel_launch(void* const* d_in, const int* in_sizes, int n_in,
                              void* d_out, int out_size) {
    const float* z = (const float*)d_in[0];
    const float* cb = (const float*)d_in[1];
    float* out = (float*)d_out;

    int nrows = in_sizes[0] / DIMS;  // 65536
    cudaFuncSetAttribute(vq_kernel, cudaFuncAttributeMaxDynamicSharedMemorySize,
                         SMEM_TOTAL);
    prep_kernel<<<128, 256>>>(cb);
    vq_kernel<<<nrows / BM, NTHREADS, SMEM_TOTAL>>>(z, cb, out);
    rescan_kernel<<<256, 256>>>(z, cb, out);
    hist_kernel<<<(nrows + 255) / 256, 256>>>(nrows);
    long nd = (long)nrows * DIMS;
    if ((long)out_size >= nd + 2)
        perp_kernel<<<1, KCODES>>>(out, (int)nd, (float)nrows);
}

// round 7
// speedup vs baseline: 1.4484x; 1.1579x over previous
#include <cuda_runtime.h>
#include <cuda_bf16.h>
#include <cstdint>
#include <math.h>

#define DIMS 256
#define KCODES 1024
#define NROWS_MAX 65536
#define BM 128
#define BN 128
#define NTHREADS 512
#define MARGIN 0.125f

#define A_ROW_B 1040                      // 512 bf16 data + 8 pad, bytes
#define A_BYTES (BM * A_ROW_B)            // 133120
#define B_ROW_B 144                       // 64 bf16 data + 8 pad, bytes
#define B_CHUNKB (BN * B_ROW_B)           // 18432
#define DSMEM_BYTES (A_BYTES + 2 * B_CHUNKB + 1024)

typedef unsigned int u32;

__device__ float d_cnorm[KCODES];
__device__ float d_counts[KCODES];
__device__ __nv_bfloat16 d_cbs[KCODES * 512];  // [code][ch(0..255)|cl(256..511)]
__device__ int d_idx[NROWS_MAX];
__device__ int d_flagList[NROWS_MAX];
__device__ int d_flagCount;

// ---------------- helpers ----------------
__device__ __forceinline__ u32 smem_u32(const void* p) {
    u32 a;
    asm("{ .reg .u64 t; cvta.to.shared.u64 t, %1; cvt.u32.u64 %0, t; }"
        : "=r"(a) : "l"(p));
    return a;
}
__device__ __forceinline__ void cpasync16(u32 dst, const void* src) {
    asm volatile("cp.async.cg.shared.global [%0], [%1], 16;"
                 :: "r"(dst), "l"(src) : "memory");
}
__device__ __forceinline__ void cp_commit() {
    asm volatile("cp.async.commit_group;" ::: "memory");
}
__device__ __forceinline__ void cp_wait0() {
    asm volatile("cp.async.wait_group 0;" ::: "memory");
}
__device__ __forceinline__ void mma_bf16(float* c, const u32* a, u32 b0, u32 b1) {
    asm volatile(
        "mma.sync.aligned.m16n8k16.row.col.f32.bf16.bf16.f32 "
        "{%0,%1,%2,%3}, {%4,%5,%6,%7}, {%8,%9}, {%0,%1,%2,%3};"
        : "+f"(c[0]), "+f"(c[1]), "+f"(c[2]), "+f"(c[3])
        : "r"(a[0]), "r"(a[1]), "r"(a[2]), "r"(a[3]), "r"(b0), "r"(b1));
}

// ---------------------------------------------------------------------------
// prep: zero counts/flags, ||c||^2, split codebook to bf16 hi/lo
// ---------------------------------------------------------------------------
__global__ void prep_kernel(const float* __restrict__ cb) {
    int gtid = blockIdx.x * blockDim.x + threadIdx.x;
    if (gtid < KCODES) d_counts[gtid] = 0.0f;
    if (gtid == 0) d_flagCount = 0;
    int w = gtid >> 5;
    int lane = threadIdx.x & 31;
    if (w < KCODES) {
        const float* r = cb + (size_t)w * DIMS;
        float s = 0.0f;
        #pragma unroll
        for (int i = 0; i < DIMS / 32; i++) {
            int d = lane + i * 32;
            float v = r[d];
            s = fmaf(v, v, s);
            __nv_bfloat16 h = __float2bfloat16(v);
            __nv_bfloat16 l = __float2bfloat16(v - __bfloat162float(h));
            d_cbs[(size_t)w * 512 + d] = h;
            d_cbs[(size_t)w * 512 + 256 + d] = l;
        }
        #pragma unroll
        for (int off = 16; off > 0; off >>= 1)
            s += __shfl_xor_sync(0xFFFFFFFFu, s, off);
        if (lane == 0) d_cnorm[w] = s;
    }
}

// ---------------------------------------------------------------------------
// main: bf16-split HMMA GEMM (16 warps, cp.async double-buffered B)
// ---------------------------------------------------------------------------
__global__ __launch_bounds__(NTHREADS, 1)
void vq_kernel(const float* __restrict__ z, const float* __restrict__ cb,
               float* __restrict__ out) {
    extern __shared__ char raw[];
    char* dsm = (char*)(((uintptr_t)raw + 1023) & ~(uintptr_t)1023);
    char* Ab = dsm;                         // 130 KB z-split, resident
    char* Bb = dsm + A_BYTES;               // 2 x 18 KB B buffers
    // reduction arrays alias the B buffers (used only after GEMM)
    float* redV1 = (float*)Bb;
    float* redV2 = redV1 + BM * 16;
    int*   redI  = (int*)(redV2 + BM * 16);
    __shared__ int sIdx[BM];

    const int tid = threadIdx.x;
    const int lane = tid & 31;
    const int wid = tid >> 5;               // 0..15
    const int warpRow = wid & 3;            // 4 row-warps x 32 rows
    const int warpCol = wid >> 2;           // 4 col-warps x 32 cols
    const int g = lane >> 2;                // 0..7
    const int tig = lane & 3;               // 0..3
    const int rowBase = blockIdx.x * BM;
    const u32 B_u32 = smem_u32(Bb);

    // ---- build A: split z into bf16 hi|lo, coalesced float2 loads ----
    for (int i = tid; i < BM * 128; i += NTHREADS) {
        int r = i >> 7, d2 = i & 127;
        float2 f = ((const float2*)(z + (size_t)(rowBase + r) * DIMS))[d2];
        __nv_bfloat16 h0 = __float2bfloat16(f.x);
        __nv_bfloat16 h1 = __float2bfloat16(f.y);
        __nv_bfloat16 l0 = __float2bfloat16(f.x - __bfloat162float(h0));
        __nv_bfloat16 l1 = __float2bfloat16(f.y - __bfloat162float(h1));
        u32 uh = (u32)__bfloat16_as_ushort(h0) | ((u32)__bfloat16_as_ushort(h1) << 16);
        u32 ul = (u32)__bfloat16_as_ushort(l0) | ((u32)__bfloat16_as_ushort(l1) << 16);
        char* arow = Ab + r * A_ROW_B;
        *(u32*)(arow + d2 * 4) = uh;
        *(u32*)(arow + 512 + d2 * 4) = ul;
    }
    __syncthreads();

    float best1[4], best2[4];
    int idx1[4];
    #pragma unroll
    for (int i = 0; i < 4; i++) { best1[i] = 3.4e38f; best2[i] = 3.4e38f; idx1[i] = 0; }

    // B loader: tid -> (code row, 32B quarter)
    const int bRow = tid >> 2;
    const int part = tid & 3;

    for (int chnk = 0; chnk < KCODES / BN; chnk++) {
        float acc[2][4][4];
        #pragma unroll
        for (int mf = 0; mf < 2; mf++)
            #pragma unroll
            for (int nf = 0; nf < 4; nf++)
                #pragma unroll
                for (int q = 0; q < 4; q++) acc[mf][nf][q] = 0.0f;

        const __nv_bfloat16* gRow = d_cbs + (size_t)(chnk * BN + bRow) * 512 + part * 16;
        const u32 dstBase = B_u32 + bRow * B_ROW_B + part * 32;

        // prologue: issue step 0 -> buf0
        {
            const __nv_bfloat16* src = gRow;   // s=0: bOff=0
            cpasync16(dstBase, src);
            cpasync16(dstBase + 16, src + 8);
            cp_commit();
        }

        #pragma unroll 1
        for (int s = 0; s < 12; s++) {
            cp_wait0();
            __syncthreads();
            if (s < 11) {
                int ns = s + 1;
                int bOff = (ns < 4) ? ns * 64 : (ns < 8 ? 256 + (ns - 4) * 64
                                                        : (ns - 8) * 64);
                const __nv_bfloat16* src = gRow + bOff;
                u32 dst = dstBase + ((ns & 1) ? B_CHUNKB : 0);
                cpasync16(dst, src);
                cpasync16(dst + 16, src + 8);
                cp_commit();
            }
            // compute step s
            const int aOff = (s < 8) ? (s & 3) * 64 : 256 + (s & 3) * 64;
            const char* Abase = Ab + (warpRow * 32) * A_ROW_B + aOff * 2;
            const char* Bbase = Bb + (s & 1) * B_CHUNKB + (warpCol * 32) * B_ROW_B;
            #pragma unroll
            for (int kk = 0; kk < 4; kk++) {
                const int kb = (kk * 16 + tig * 2) * 2;
                u32 a[2][4];
                #pragma unroll
                for (int mf = 0; mf < 2; mf++) {
                    const char* ap = Abase + (mf * 16 + g) * A_ROW_B + kb;
                    a[mf][0] = *(const u32*)(ap);
                    a[mf][1] = *(const u32*)(ap + 8 * A_ROW_B);
                    a[mf][2] = *(const u32*)(ap + 16);
                    a[mf][3] = *(const u32*)(ap + 8 * A_ROW_B + 16);
                }
                #pragma unroll
                for (int nf = 0; nf < 4; nf++) {
                    const char* bp = Bbase + (nf * 8 + g) * B_ROW_B + kb;
                    u32 b0 = *(const u32*)(bp);
                    u32 b1 = *(const u32*)(bp + 16);
                    mma_bf16(acc[0][nf], a[0], b0, b1);
                    mma_bf16(acc[1][nf], a[1], b0, b1);
                }
            }
        }

        // fold chunk into per-row top-2: cost = ||c||^2 - 2*dot
        #pragma unroll
        for (int nf = 0; nf < 4; nf++) {
            #pragma unroll
            for (int cc = 0; cc < 2; cc++) {
                int col = chnk * BN + warpCol * 32 + nf * 8 + tig * 2 + cc;
                float cn = __ldg(&d_cnorm[col]);
                #pragma unroll
                for (int mf = 0; mf < 2; mf++) {
                    #pragma unroll
                    for (int sub = 0; sub < 2; sub++) {
                        float cost = fmaf(-2.0f, acc[mf][nf][sub * 2 + cc], cn);
                        int rr = mf * 2 + sub;
                        if (cost < best1[rr]) {
                            best2[rr] = best1[rr];
                            best1[rr] = cost; idx1[rr] = col;
                        } else if (cost < best2[rr]) {
                            best2[rr] = cost;
                        }
                    }
                }
            }
        }
    }

    __syncthreads();   // all GEMM reads of B buffers done; alias as reduction

    const int slot = warpCol * 4 + tig;   // 16 candidates per row
    #pragma unroll
    for (int rr = 0; rr < 4; rr++) {
        int r = warpRow * 32 + (rr >> 1) * 16 + (rr & 1) * 8 + g;
        redV1[r * 16 + slot] = best1[rr];
        redV2[r * 16 + slot] = best2[rr];
        redI[r * 16 + slot] = idx1[rr];
    }
    __syncthreads();

    if (tid < BM) {
        float b1 = 3.4e38f, b2 = 3.4e38f;
        int i1 = 0x7FFFFFFF;
        #pragma unroll
        for (int t = 0; t < 16; t++) {
            float v1 = redV1[tid * 16 + t];
            float v2 = redV2[tid * 16 + t];
            int ix = redI[tid * 16 + t];
            if (v1 < b1) {
                b2 = fminf(b1, v2);
                b1 = v1; i1 = ix;
            } else if (v1 == b1) {
                i1 = min(i1, ix);
                b2 = fminf(b2, v2);
            } else {
                b2 = fminf(b2, fminf(v1, v2));
            }
        }
        sIdx[tid] = i1;
        d_idx[rowBase + tid] = i1;
        if (b2 - b1 < MARGIN) {
            int p = atomicAdd(&d_flagCount, 1);
            d_flagList[p] = rowBase + tid;
        }
    }
    __syncthreads();

    // gather z_q rows
    const float4* cb4 = (const float4*)cb;
    float4* out4 = (float4*)out;
    for (int i = tid; i < BM * 64; i += NTHREADS) {
        int r = i >> 6, q = i & 63;
        int code = sIdx[r];
        out4[(size_t)(rowBase + r) * 64 + q] = cb4[(size_t)code * 64 + q];
    }
}

// ---------------------------------------------------------------------------
// rescan: exact fp32 scan for ambiguous rows, 16 rows per block-iteration
// ---------------------------------------------------------------------------
__global__ void rescan_kernel(const float* __restrict__ z,
                              const float* __restrict__ cb,
                              float* __restrict__ out) {
    __shared__ float zr[16][DIMS];
    __shared__ float sRV[16][8];
    __shared__ int   sRI[16][8];
    __shared__ int   sRow[16];
    __shared__ int   sFix[16];

    const int tid = threadIdx.x;
    const int lane = tid & 31;
    const int wrp = tid >> 5;
    const int cnt = d_flagCount;

    for (int base = blockIdx.x * 16; base < cnt; base += gridDim.x * 16) {
        const int nr = min(16, cnt - base);
        for (int i = tid; i < 16 * DIMS; i += 256)
            ((float*)zr)[i] = 0.0f;
        __syncthreads();
        if (tid < nr) sRow[tid] = d_flagList[base + tid];
        __syncthreads();
        for (int i = tid; i < nr * DIMS; i += 256)
            zr[i >> 8][i & 255] = z[(size_t)sRow[i >> 8] * DIMS + (i & 255)];
        __syncthreads();

        float bb[16]; int bi[16];
        #pragma unroll
        for (int r = 0; r < 16; r++) { bb[r] = 3.4e38f; bi[r] = 0x7FFFFFFF; }

        #pragma unroll
        for (int cc = 0; cc < 4; cc++) {
            const int c = tid + cc * 256;
            const float4* cp = (const float4*)(cb + (size_t)c * DIMS);
            #pragma unroll
            for (int pass = 0; pass < 2; pass++) {
                float dot[8];
                #pragma unroll
                for (int r = 0; r < 8; r++) dot[r] = 0.0f;
                for (int q = 0; q < 64; q++) {
                    float4 cv = cp[q];
                    #pragma unroll
                    for (int r = 0; r < 8; r++) {
                        float4 zv = *(const float4*)&zr[pass * 8 + r][q * 4];
                        dot[r] = fmaf(zv.x, cv.x, dot[r]);
                        dot[r] = fmaf(zv.y, cv.y, dot[r]);
                        dot[r] = fmaf(zv.z, cv.z, dot[r]);
                        dot[r] = fmaf(zv.w, cv.w, dot[r]);
                    }
                }
                float cn = __ldg(&d_cnorm[c]);
                #pragma unroll
                for (int r = 0; r < 8; r++) {
                    float cost = fmaf(-2.0f, dot[r], cn);
                    int rr = pass * 8 + r;
                    if (cost < bb[rr] || (cost == bb[rr] && c < bi[rr])) {
                        bb[rr] = cost; bi[rr] = c;
                    }
                }
            }
        }
        #pragma unroll
        for (int off = 16; off > 0; off >>= 1) {
            #pragma unroll
            for (int r = 0; r < 16; r++) {
                float vv = __shfl_xor_sync(0xFFFFFFFFu, bb[r], off);
                int ii = __shfl_xor_sync(0xFFFFFFFFu, bi[r], off);
                if (vv < bb[r] || (vv == bb[r] && ii < bi[r])) { bb[r] = vv; bi[r] = ii; }
            }
        }
        if (lane == 0) {
            #pragma unroll
            for (int r = 0; r < 16; r++) { sRV[r][wrp] = bb[r]; sRI[r][wrp] = bi[r]; }
        }
        __syncthreads();
        if (tid < nr) {
            float bv = 3.4e38f; int bix = 0x7FFFFFFF;
            #pragma unroll
            for (int w = 0; w < 8; w++) {
                float v = sRV[tid][w]; int ix = sRI[tid][w];
                if (v < bv || (v == bv && ix < bix)) { bv = v; bix = ix; }
            }
            d_idx[sRow[tid]] = bix;
            sFix[tid] = bix;
        }
        __syncthreads();
        const float4* cb4 = (const float4*)cb;
        float4* out4 = (float4*)out;
        for (int i = tid; i < nr * 64; i += 256) {
            int r = i >> 6, q = i & 63;
            out4[(size_t)sRow[r] * 64 + q] = cb4[(size_t)sFix[r] * 64 + q];
        }
        __syncthreads();
    }
}

// ---------------------------------------------------------------------------
__global__ void hist_kernel(int nrows) {
    int i = blockIdx.x * blockDim.x + threadIdx.x;
    if (i < nrows) atomicAdd(&d_counts[d_idx[i]], 1.0f);
}

__global__ void perp_kernel(float* __restrict__ out, int nd, float n) {
    __shared__ float s[KCODES];
    int t = threadIdx.x;
    float e = d_counts[t] / n;
    s[t] = e * logf(e + 1e-10f);
    __syncthreads();
    for (int st = KCODES / 2; st > 0; st >>= 1) {
        if (t < st) s[t] += s[t + st];
        __syncthreads();
    }
    if (t == 0) {
        out[nd] = 0.0f;
        out[nd + 1] = expf(-s[0]);
    }
}

extern "C" void kernel_launch(void* const* d_in, const int* in_sizes, int n_in,
                              void* d_out, int out_size) {
    const float* z = (const float*)d_in[0];
    const float* cb = (const float*)d_in[1];
    float* out = (float*)d_out;

    int nrows = in_sizes[0] / DIMS;  // 65536
    cudaFuncSetAttribute(vq_kernel, cudaFuncAttributeMaxDynamicSharedMemorySize,
                         DSMEM_BYTES);
    prep_kernel<<<128, 256>>>(cb);
    vq_kernel<<<nrows / BM, NTHREADS, DSMEM_BYTES>>>(z, cb, out);
    rescan_kernel<<<128, 256>>>(z, cb, out);
    hist_kernel<<<(nrows + 255) / 256, 256>>>(nrows);
    long nd = (long)nrows * DIMS;
    if ((long)out_size >= nd + 2)
        perp_kernel<<<1, KCODES>>>(out, (int)nd, (float)nrows);
}

// round 8
// speedup vs baseline: 2.9647x; 2.0470x over previous
#include <cuda_runtime.h>
#include <cuda_bf16.h>
#include <cuda_fp16.h>
#include <cstdint>
#include <math.h>

#define DIMS 256
#define KCODES 1024
#define NROWS_MAX 65536
#define BM 128
#define BN 128
#define NTHREADS 512
#define MARGIN 0.25f

#define A_ROW_B 528                       // 256 fp16 data (512B) + 16 pad
#define A_BYTES (BM * A_ROW_B)            // 67584
#define B_ROW_B 144                       // 64 fp16 data (128B) + 16 pad
#define B_CHUNKB (BN * B_ROW_B)           // 18432
#define DSMEM_BYTES (A_BYTES + 2 * B_CHUNKB + 1024)

typedef unsigned int u32;

__device__ float d_cnorm[KCODES];
__device__ float d_counts[KCODES];
__device__ __half d_cbh[KCODES * 256];    // fp16 codebook
__device__ int d_idx[NROWS_MAX];
__device__ int d_flagList[NROWS_MAX];
__device__ int d_flagCount;

// ---------------- helpers ----------------
__device__ __forceinline__ u32 smem_u32(const void* p) {
    u32 a;
    asm("{ .reg .u64 t; cvta.to.shared.u64 t, %1; cvt.u32.u64 %0, t; }"
        : "=r"(a) : "l"(p));
    return a;
}
__device__ __forceinline__ void cpasync16(u32 dst, const void* src) {
    asm volatile("cp.async.cg.shared.global [%0], [%1], 16;"
                 :: "r"(dst), "l"(src) : "memory");
}
__device__ __forceinline__ void cp_commit() {
    asm volatile("cp.async.commit_group;" ::: "memory");
}
__device__ __forceinline__ void cp_wait0() {
    asm volatile("cp.async.wait_group 0;" ::: "memory");
}
__device__ __forceinline__ void mma_f16(float* c, const u32* a, u32 b0, u32 b1) {
    asm volatile(
        "mma.sync.aligned.m16n8k16.row.col.f32.f16.f16.f32 "
        "{%0,%1,%2,%3}, {%4,%5,%6,%7}, {%8,%9}, {%0,%1,%2,%3};"
        : "+f"(c[0]), "+f"(c[1]), "+f"(c[2]), "+f"(c[3])
        : "r"(a[0]), "r"(a[1]), "r"(a[2]), "r"(a[3]), "r"(b0), "r"(b1));
}

// ---------------------------------------------------------------------------
// prep: zero counts/flags, ||c||^2 (fp32), codebook -> fp16
// ---------------------------------------------------------------------------
__global__ void prep_kernel(const float* __restrict__ cb) {
    int gtid = blockIdx.x * blockDim.x + threadIdx.x;
    if (gtid < KCODES) d_counts[gtid] = 0.0f;
    if (gtid == 0) d_flagCount = 0;
    int w = gtid >> 5;
    int lane = threadIdx.x & 31;
    if (w < KCODES) {
        const float* r = cb + (size_t)w * DIMS;
        float s = 0.0f;
        #pragma unroll
        for (int i = 0; i < DIMS / 32; i++) {
            int d = lane + i * 32;
            float v = r[d];
            s = fmaf(v, v, s);
            d_cbh[(size_t)w * DIMS + d] = __float2half(v);
        }
        #pragma unroll
        for (int off = 16; off > 0; off >>= 1)
            s += __shfl_xor_sync(0xFFFFFFFFu, s, off);
        if (lane == 0) d_cnorm[w] = s;
    }
}

// ---------------------------------------------------------------------------
// main: single-pass fp16 HMMA GEMM + top-2 + flag + gather + histogram
// ---------------------------------------------------------------------------
__global__ __launch_bounds__(NTHREADS, 1)
void vq_kernel(const float* __restrict__ z, const float* __restrict__ cb,
               float* __restrict__ out) {
    extern __shared__ char raw[];
    char* dsm = (char*)(((uintptr_t)raw + 1023) & ~(uintptr_t)1023);
    char* Ab = dsm;                         // 66 KB z fp16, resident
    char* Bb = dsm + A_BYTES;               // 2 x 18 KB B buffers
    // reduction arrays alias B buffers (used only after GEMM)
    float* redV1 = (float*)Bb;
    float* redV2 = redV1 + BM * 16;
    int*   redI  = (int*)(redV2 + BM * 16);
    __shared__ int sIdx[BM];

    const int tid = threadIdx.x;
    const int lane = tid & 31;
    const int wid = tid >> 5;               // 0..15
    const int warpRow = wid & 3;            // 4 row-warps x 32 rows
    const int warpCol = wid >> 2;           // 4 col-warps x 32 cols
    const int g = lane >> 2;                // 0..7
    const int tig = lane & 3;               // 0..3
    const int rowBase = blockIdx.x * BM;
    const u32 B_u32 = smem_u32(Bb);

    // ---- build A: z -> fp16, coalesced float2 loads ----
    for (int i = tid; i < BM * 128; i += NTHREADS) {
        int r = i >> 7, d2 = i & 127;
        float2 f = ((const float2*)(z + (size_t)(rowBase + r) * DIMS))[d2];
        __half h0 = __float2half(f.x);
        __half h1 = __float2half(f.y);
        u32 uh = (u32)__half_as_ushort(h0) | ((u32)__half_as_ushort(h1) << 16);
        *(u32*)(Ab + r * A_ROW_B + d2 * 4) = uh;
    }
    __syncthreads();

    float best1[4], best2[4];
    int idx1[4];
    #pragma unroll
    for (int i = 0; i < 4; i++) { best1[i] = 3.4e38f; best2[i] = 3.4e38f; idx1[i] = 0; }

    // B loader: tid -> (code row, 32B quarter)
    const int bRow = tid >> 2;
    const int part = tid & 3;

    for (int chnk = 0; chnk < KCODES / BN; chnk++) {
        float acc[2][4][4];
        #pragma unroll
        for (int mf = 0; mf < 2; mf++)
            #pragma unroll
            for (int nf = 0; nf < 4; nf++)
                #pragma unroll
                for (int q = 0; q < 4; q++) acc[mf][nf][q] = 0.0f;

        const __half* gRow = d_cbh + (size_t)(chnk * BN + bRow) * DIMS + part * 16;
        const u32 dstBase = B_u32 + bRow * B_ROW_B + part * 32;

        // prologue: issue step 0 -> buf0
        cpasync16(dstBase, gRow);
        cpasync16(dstBase + 16, gRow + 8);
        cp_commit();

        #pragma unroll
        for (int s = 0; s < 4; s++) {
            cp_wait0();
            __syncthreads();
            if (s < 3) {
                const __half* src = gRow + (s + 1) * 64;
                u32 dst = dstBase + (((s + 1) & 1) ? B_CHUNKB : 0);
                cpasync16(dst, src);
                cpasync16(dst + 16, src + 8);
                cp_commit();
            }
            // compute step s (64 dims)
            const char* Abase = Ab + (warpRow * 32) * A_ROW_B + s * 128;
            const char* Bbase = Bb + (s & 1) * B_CHUNKB + (warpCol * 32) * B_ROW_B;
            #pragma unroll
            for (int kk = 0; kk < 4; kk++) {
                const int kb = (kk * 16 + tig * 2) * 2;
                u32 a[2][4];
                #pragma unroll
                for (int mf = 0; mf < 2; mf++) {
                    const char* ap = Abase + (mf * 16 + g) * A_ROW_B + kb;
                    a[mf][0] = *(const u32*)(ap);
                    a[mf][1] = *(const u32*)(ap + 8 * A_ROW_B);
                    a[mf][2] = *(const u32*)(ap + 16);
                    a[mf][3] = *(const u32*)(ap + 8 * A_ROW_B + 16);
                }
                #pragma unroll
                for (int nf = 0; nf < 4; nf++) {
                    const char* bp = Bbase + (nf * 8 + g) * B_ROW_B + kb;
                    u32 b0 = *(const u32*)(bp);
                    u32 b1 = *(const u32*)(bp + 16);
                    mma_f16(acc[0][nf], a[0], b0, b1);
                    mma_f16(acc[1][nf], a[1], b0, b1);
                }
            }
        }

        // fold chunk into per-row top-2: cost = ||c||^2 - 2*dot
        #pragma unroll
        for (int nf = 0; nf < 4; nf++) {
            #pragma unroll
            for (int cc = 0; cc < 2; cc++) {
                int col = chnk * BN + warpCol * 32 + nf * 8 + tig * 2 + cc;
                float cn = __ldg(&d_cnorm[col]);
                #pragma unroll
                for (int mf = 0; mf < 2; mf++) {
                    #pragma unroll
                    for (int sub = 0; sub < 2; sub++) {
                        float cost = fmaf(-2.0f, acc[mf][nf][sub * 2 + cc], cn);
                        int rr = mf * 2 + sub;
                        if (cost < best1[rr]) {
                            best2[rr] = best1[rr];
                            best1[rr] = cost; idx1[rr] = col;
                        } else if (cost < best2[rr]) {
                            best2[rr] = cost;
                        }
                    }
                }
            }
        }
    }

    __syncthreads();   // GEMM reads of B buffers done; alias as reduction

    const int slot = warpCol * 4 + tig;   // 16 candidates per row
    #pragma unroll
    for (int rr = 0; rr < 4; rr++) {
        int r = warpRow * 32 + (rr >> 1) * 16 + (rr & 1) * 8 + g;
        redV1[r * 16 + slot] = best1[rr];
        redV2[r * 16 + slot] = best2[rr];
        redI[r * 16 + slot] = idx1[rr];
    }
    __syncthreads();

    if (tid < BM) {
        float b1 = 3.4e38f, b2 = 3.4e38f;
        int i1 = 0x7FFFFFFF;
        #pragma unroll
        for (int t = 0; t < 16; t++) {
            float v1 = redV1[tid * 16 + t];
            float v2 = redV2[tid * 16 + t];
            int ix = redI[tid * 16 + t];
            if (v1 < b1) {
                b2 = fminf(b1, v2);
                b1 = v1; i1 = ix;
            } else if (v1 == b1) {
                i1 = min(i1, ix);
                b2 = fminf(b2, v2);
            } else {
                b2 = fminf(b2, fminf(v1, v2));
            }
        }
        sIdx[tid] = i1;
        d_idx[rowBase + tid] = i1;
        atomicAdd(&d_counts[i1], 1.0f);
        if (b2 - b1 < MARGIN) {
            int p = atomicAdd(&d_flagCount, 1);
            d_flagList[p] = rowBase + tid;
        }
    }
    __syncthreads();

    // gather z_q rows
    const float4* cb4 = (const float4*)cb;
    float4* out4 = (float4*)out;
    for (int i = tid; i < BM * 64; i += NTHREADS) {
        int r = i >> 6, q = i & 63;
        int code = sIdx[r];
        out4[(size_t)(rowBase + r) * 64 + q] = cb4[(size_t)code * 64 + q];
    }
}

// ---------------------------------------------------------------------------
// rescan: exact fp32 scan for ambiguous rows, 16 rows per block-iteration
// fixes d_idx, d_counts, and out for any row whose index changes
// ---------------------------------------------------------------------------
__global__ void rescan_kernel(const float* __restrict__ z,
                              const float* __restrict__ cb,
                              float* __restrict__ out) {
    __shared__ float zr[16][DIMS];
    __shared__ float sRV[16][8];
    __shared__ int   sRI[16][8];
    __shared__ int   sRow[16];
    __shared__ int   sFix[16];

    const int tid = threadIdx.x;
    const int lane = tid & 31;
    const int wrp = tid >> 5;
    const int cnt = d_flagCount;

    for (int base = blockIdx.x * 16; base < cnt; base += gridDim.x * 16) {
        const int nr = min(16, cnt - base);
        for (int i = tid; i < 16 * DIMS; i += 256)
            ((float*)zr)[i] = 0.0f;
        __syncthreads();
        if (tid < nr) sRow[tid] = d_flagList[base + tid];
        __syncthreads();
        for (int i = tid; i < nr * DIMS; i += 256)
            zr[i >> 8][i & 255] = z[(size_t)sRow[i >> 8] * DIMS + (i & 255)];
        __syncthreads();

        float bb[16]; int bi[16];
        #pragma unroll
        for (int r = 0; r < 16; r++) { bb[r] = 3.4e38f; bi[r] = 0x7FFFFFFF; }

        #pragma unroll
        for (int cc = 0; cc < 4; cc++) {
            const int c = tid + cc * 256;
            const float4* cp = (const float4*)(cb + (size_t)c * DIMS);
            #pragma unroll
            for (int pass = 0; pass < 2; pass++) {
                float dot[8];
                #pragma unroll
                for (int r = 0; r < 8; r++) dot[r] = 0.0f;
                for (int q = 0; q < 64; q++) {
                    float4 cv = cp[q];
                    #pragma unroll
                    for (int r = 0; r < 8; r++) {
                        float4 zv = *(const float4*)&zr[pass * 8 + r][q * 4];
                        dot[r] = fmaf(zv.x, cv.x, dot[r]);
                        dot[r] = fmaf(zv.y, cv.y, dot[r]);
                        dot[r] = fmaf(zv.z, cv.z, dot[r]);
                        dot[r] = fmaf(zv.w, cv.w, dot[r]);
                    }
                }
                float cn = __ldg(&d_cnorm[c]);
                #pragma unroll
                for (int r = 0; r < 8; r++) {
                    float cost = fmaf(-2.0f, dot[r], cn);
                    int rr = pass * 8 + r;
                    if (cost < bb[rr] || (cost == bb[rr] && c < bi[rr])) {
                        bb[rr] = cost; bi[rr] = c;
                    }
                }
            }
        }
        #pragma unroll
        for (int off = 16; off > 0; off >>= 1) {
            #pragma unroll
            for (int r = 0; r < 16; r++) {
                float vv = __shfl_xor_sync(0xFFFFFFFFu, bb[r], off);
                int ii = __shfl_xor_sync(0xFFFFFFFFu, bi[r], off);
                if (vv < bb[r] || (vv == bb[r] && ii < bi[r])) { bb[r] = vv; bi[r] = ii; }
            }
        }
        if (lane == 0) {
            #pragma unroll
            for (int r = 0; r < 16; r++) { sRV[r][wrp] = bb[r]; sRI[r][wrp] = bi[r]; }
        }
        __syncthreads();
        if (tid < nr) {
            float bv = 3.4e38f; int bix = 0x7FFFFFFF;
            #pragma unroll
            for (int w = 0; w < 8; w++) {
                float v = sRV[tid][w]; int ix = sRI[tid][w];
                if (v < bv || (v == bv && ix < bix)) { bv = v; bix = ix; }
            }
            int old = d_idx[sRow[tid]];
            sFix[tid] = bix;
            if (bix != old) {
                d_idx[sRow[tid]] = bix;
                atomicAdd(&d_counts[old], -1.0f);
                atomicAdd(&d_counts[bix], 1.0f);
            }
        }
        __syncthreads();
        const float4* cb4 = (const float4*)cb;
        float4* out4 = (float4*)out;
        for (int i = tid; i < nr * 64; i += 256) {
            int r = i >> 6, q = i & 63;
            out4[(size_t)sRow[r] * 64 + q] = cb4[(size_t)sFix[r] * 64 + q];
        }
        __syncthreads();
    }
}

// ---------------------------------------------------------------------------
__global__ void perp_kernel(float* __restrict__ out, int nd, float n) {
    __shared__ float s[KCODES];
    int t = threadIdx.x;
    float e = d_counts[t] / n;
    s[t] = e * logf(e + 1e-10f);
    __syncthreads();
    for (int st = KCODES / 2; st > 0; st >>= 1) {
        if (t < st) s[t] += s[t + st];
        __syncthreads();
    }
    if (t == 0) {
        out[nd] = 0.0f;
        out[nd + 1] = expf(-s[0]);
    }
}

extern "C" void kernel_launch(void* const* d_in, const int* in_sizes, int n_in,
                              void* d_out, int out_size) {
    const float* z = (const float*)d_in[0];
    const float* cb = (const float*)d_in[1];
    float* out = (float*)d_out;

    int nrows = in_sizes[0] / DIMS;  // 65536
    cudaFuncSetAttribute(vq_kernel, cudaFuncAttributeMaxDynamicSharedMemorySize,
                         DSMEM_BYTES);
    prep_kernel<<<128, 256>>>(cb);
    vq_kernel<<<nrows / BM, NTHREADS, DSMEM_BYTES>>>(z, cb, out);
    rescan_kernel<<<256, 256>>>(z, cb, out);
    long nd = (long)nrows * DIMS;
    if ((long)out_size >= nd + 2)
        perp_kernel<<<1, KCODES>>>(out, (int)nd, (float)nrows);
}

// round 10
// speedup vs baseline: 3.3136x; 1.1177x over previous
#include <cuda_runtime.h>
#include <cuda_bf16.h>
#include <cuda_fp16.h>
#include <cstdint>
#include <math.h>

#define DIMS 256
#define KCODES 1024
#define NROWS_MAX 65536
#define BM 128
#define BN 128
#define NTHREADS 512
#define MARGIN 0.25f

#define A_ROW_B 528                       // 256 fp16 data (512B) + 16 pad
#define A_BYTES (BM * A_ROW_B)            // 67584
#define B_ROW_B 144                       // 64 fp16 data (128B) + 16 pad
#define B_CHUNKB (BN * B_ROW_B)           // 18432
#define DSMEM_BYTES (A_BYTES + 2 * B_CHUNKB + 1024)

typedef unsigned int u32;

__device__ float d_cnorm[KCODES];
__device__ float d_counts[KCODES];
__device__ __half d_cbh[KCODES * 256];    // fp16 codebook
__device__ int d_idx[NROWS_MAX];
__device__ int d_flagList[NROWS_MAX];
__device__ int d_flagCount;

// ---------------- helpers ----------------
__device__ __forceinline__ u32 smem_u32(const void* p) {
    u32 a;
    asm("{ .reg .u64 t; cvta.to.shared.u64 t, %1; cvt.u32.u64 %0, t; }"
        : "=r"(a) : "l"(p));
    return a;
}
__device__ __forceinline__ void cpasync16(u32 dst, const void* src) {
    asm volatile("cp.async.cg.shared.global [%0], [%1], 16;"
                 :: "r"(dst), "l"(src) : "memory");
}
__device__ __forceinline__ void cp_commit() {
    asm volatile("cp.async.commit_group;" ::: "memory");
}
__device__ __forceinline__ void cp_wait0() {
    asm volatile("cp.async.wait_group 0;" ::: "memory");
}
__device__ __forceinline__ void mma_f16(float* c, const u32* a, u32 b0, u32 b1) {
    asm volatile(
        "mma.sync.aligned.m16n8k16.row.col.f32.f16.f16.f32 "
        "{%0,%1,%2,%3}, {%4,%5,%6,%7}, {%8,%9}, {%0,%1,%2,%3};"
        : "+f"(c[0]), "+f"(c[1]), "+f"(c[2]), "+f"(c[3])
        : "r"(a[0]), "r"(a[1]), "r"(a[2]), "r"(a[3]), "r"(b0), "r"(b1));
}
__device__ __forceinline__ void ldsm_x4(u32& r0, u32& r1, u32& r2, u32& r3, u32 a) {
    asm volatile("ldmatrix.sync.aligned.m8n8.x4.shared.b16 {%0,%1,%2,%3}, [%4];"
        : "=r"(r0), "=r"(r1), "=r"(r2), "=r"(r3) : "r"(a));
}

// ---------------------------------------------------------------------------
// prep: zero counts/flags, ||c||^2 (fp32), codebook -> fp16
// ---------------------------------------------------------------------------
__global__ void prep_kernel(const float* __restrict__ cb) {
    int gtid = blockIdx.x * blockDim.x + threadIdx.x;
    if (gtid < KCODES) d_counts[gtid] = 0.0f;
    if (gtid == 0) d_flagCount = 0;
    int w = gtid >> 5;
    int lane = threadIdx.x & 31;
    if (w < KCODES) {
        const float* r = cb + (size_t)w * DIMS;
        float s = 0.0f;
        #pragma unroll
        for (int i = 0; i < DIMS / 32; i++) {
            int d = lane + i * 32;
            float v = r[d];
            s = fmaf(v, v, s);
            d_cbh[(size_t)w * DIMS + d] = __float2half(v);
        }
        #pragma unroll
        for (int off = 16; off > 0; off >>= 1)
            s += __shfl_xor_sync(0xFFFFFFFFu, s, off);
        if (lane == 0) d_cnorm[w] = s;
    }
}

// ---------------------------------------------------------------------------
// main: fp16 HMMA GEMM (ldmatrix fragments) + top-2 + flag + gather + hist
// ---------------------------------------------------------------------------
__global__ __launch_bounds__(NTHREADS, 1)
void vq_kernel(const float* __restrict__ z, const float* __restrict__ cb,
               float* __restrict__ out) {
    extern __shared__ char raw[];
    char* dsm = (char*)(((uintptr_t)raw + 1023) & ~(uintptr_t)1023);
    char* Ab = dsm;                         // 66 KB z fp16, resident
    char* Bb = dsm + A_BYTES;               // 2 x 18 KB B buffers
    float* redV1 = (float*)Bb;              // aliases B bufs post-GEMM
    float* redV2 = redV1 + BM * 16;
    int*   redI  = (int*)(redV2 + BM * 16);
    __shared__ int sIdx[BM];

    const int tid = threadIdx.x;
    const int lane = tid & 31;
    const int wid = tid >> 5;               // 0..15
    const int warpRow = wid & 3;            // 4 row-warps x 32 rows
    const int warpCol = wid >> 2;           // 4 col-warps x 32 cols
    const int g = lane >> 2;                // 0..7
    const int tig = lane & 3;               // 0..3
    const int rowBase = blockIdx.x * BM;
    const u32 A_u32 = smem_u32(Ab);
    const u32 B_u32 = smem_u32(Bb);

    // ---- build A: z -> fp16, coalesced float2 loads ----
    for (int i = tid; i < BM * 128; i += NTHREADS) {
        int r = i >> 7, d2 = i & 127;
        float2 f = ((const float2*)(z + (size_t)(rowBase + r) * DIMS))[d2];
        __half h0 = __float2half(f.x);
        __half h1 = __float2half(f.y);
        u32 uh = (u32)__half_as_ushort(h0) | ((u32)__half_as_ushort(h1) << 16);
        *(u32*)(Ab + r * A_ROW_B + d2 * 4) = uh;
    }
    __syncthreads();

    float best1[4], best2[4];
    int idx1[4];
    #pragma unroll
    for (int i = 0; i < 4; i++) { best1[i] = 3.4e38f; best2[i] = 3.4e38f; idx1[i] = 0; }

    // ldmatrix lane-address bases
    // A: lane -> row = warpRow*32 + (lane&15), koff = (lane&16) ? 8 fp16 : 0
    const u32 aLane = A_u32 + (warpRow * 32 + (lane & 15)) * A_ROW_B
                            + ((lane & 16) ? 16 : 0);
    // B: lane -> n = warpCol*32 + (lane&7) + ((lane&16)?8:0), koff=(lane&8)?8:0
    const u32 bLane = B_u32 + (warpCol * 32 + (lane & 7) + ((lane & 16) ? 8 : 0)) * B_ROW_B
                            + ((lane & 8) ? 16 : 0);

    // B loader: tid -> (code row, 32B quarter)
    const int bRow = tid >> 2;
    const int part = tid & 3;

    for (int chnk = 0; chnk < KCODES / BN; chnk++) {
        float acc[2][4][4];
        #pragma unroll
        for (int mf = 0; mf < 2; mf++)
            #pragma unroll
            for (int nf = 0; nf < 4; nf++)
                #pragma unroll
                for (int q = 0; q < 4; q++) acc[mf][nf][q] = 0.0f;

        const __half* gRow = d_cbh + (size_t)(chnk * BN + bRow) * DIMS + part * 16;
        const u32 dstBase = B_u32 + bRow * B_ROW_B + part * 32;

        // prologue: issue step 0 -> buf0
        cpasync16(dstBase, gRow);
        cpasync16(dstBase + 16, gRow + 8);
        cp_commit();

        #pragma unroll
        for (int s = 0; s < 4; s++) {
            cp_wait0();
            __syncthreads();
            if (s < 3) {
                const __half* src = gRow + (s + 1) * 64;
                u32 dst = dstBase + (((s + 1) & 1) ? B_CHUNKB : 0);
                cpasync16(dst, src);
                cpasync16(dst + 16, src + 8);
                cp_commit();
            }
            const u32 aS = aLane + s * 128;                    // +64 fp16
            const u32 bS = bLane + ((s & 1) ? B_CHUNKB : 0);
            #pragma unroll
            for (int kk = 0; kk < 4; kk++) {
                u32 a0[4], a1[4], bA[4], bB[4];
                ldsm_x4(a0[0], a0[1], a0[2], a0[3], aS + kk * 32);
                ldsm_x4(a1[0], a1[1], a1[2], a1[3], aS + 16 * A_ROW_B + kk * 32);
                ldsm_x4(bA[0], bA[1], bA[2], bA[3], bS + kk * 32);
                ldsm_x4(bB[0], bB[1], bB[2], bB[3], bS + 16 * B_ROW_B + kk * 32);
                mma_f16(acc[0][0], a0, bA[0], bA[1]);
                mma_f16(acc[1][0], a1, bA[0], bA[1]);
                mma_f16(acc[0][1], a0, bA[2], bA[3]);
                mma_f16(acc[1][1], a1, bA[2], bA[3]);
                mma_f16(acc[0][2], a0, bB[0], bB[1]);
                mma_f16(acc[1][2], a1, bB[0], bB[1]);
                mma_f16(acc[0][3], a0, bB[2], bB[3]);
                mma_f16(acc[1][3], a1, bB[2], bB[3]);
            }
        }

        // fold chunk into per-row top-2: cost = ||c||^2 - 2*dot
        #pragma unroll
        for (int nf = 0; nf < 4; nf++) {
            #pragma unroll
            for (int cc = 0; cc < 2; cc++) {
                int col = chnk * BN + warpCol * 32 + nf * 8 + tig * 2 + cc;
                float cn = __ldg(&d_cnorm[col]);
                #pragma unroll
                for (int mf = 0; mf < 2; mf++) {
                    #pragma unroll
                    for (int sub = 0; sub < 2; sub++) {
                        float cost = fmaf(-2.0f, acc[mf][nf][sub * 2 + cc], cn);
                        int rr = mf * 2 + sub;
                        if (cost < best1[rr]) {
                            best2[rr] = best1[rr];
                            best1[rr] = cost; idx1[rr] = col;
                        } else if (cost < best2[rr]) {
                            best2[rr] = cost;
                        }
                    }
                }
            }
        }
    }

    __syncthreads();   // GEMM reads of B buffers done; alias as reduction

    const int slot = warpCol * 4 + tig;   // 16 candidates per row
    #pragma unroll
    for (int rr = 0; rr < 4; rr++) {
        int r = warpRow * 32 + (rr >> 1) * 16 + (rr & 1) * 8 + g;
        redV1[r * 16 + slot] = best1[rr];
        redV2[r * 16 + slot] = best2[rr];
        redI[r * 16 + slot] = idx1[rr];
    }
    __syncthreads();

    if (tid < BM) {
        float b1 = 3.4e38f, b2 = 3.4e38f;
        int i1 = 0x7FFFFFFF;
        #pragma unroll
        for (int t = 0; t < 16; t++) {
            float v1 = redV1[tid * 16 + t];
            float v2 = redV2[tid * 16 + t];
            int ix = redI[tid * 16 + t];
            if (v1 < b1) {
                b2 = fminf(b1, v2);
                b1 = v1; i1 = ix;
            } else if (v1 == b1) {
                i1 = min(i1, ix);
                b2 = fminf(b2, v2);
            } else {
                b2 = fminf(b2, fminf(v1, v2));
            }
        }
        sIdx[tid] = i1;
        d_idx[rowBase + tid] = i1;
        atomicAdd(&d_counts[i1], 1.0f);
        if (b2 - b1 < MARGIN) {
            int p = atomicAdd(&d_flagCount, 1);
            d_flagList[p] = rowBase + tid;
        }
    }
    __syncthreads();

    // gather z_q rows
    const float4* cb4 = (const float4*)cb;
    float4* out4 = (float4*)out;
    for (int i = tid; i < BM * 64; i += NTHREADS) {
        int r = i >> 6, q = i & 63;
        int code = sIdx[r];
        out4[(size_t)(rowBase + r) * 64 + q] = cb4[(size_t)code * 64 + q];
    }
}

// ---------------------------------------------------------------------------
// rescan: exact fp32 scan for ambiguous rows, 16 rows per block-iteration
// ---------------------------------------------------------------------------
__global__ void rescan_kernel(const float* __restrict__ z,
                              const float* __restrict__ cb,
                              float* __restrict__ out) {
    __shared__ float zr[16][DIMS];
    __shared__ float sRV[16][8];
    __shared__ int   sRI[16][8];
    __shared__ int   sRow[16];
    __shared__ int   sFix[16];

    const int tid = threadIdx.x;
    const int lane = tid & 31;
    const int wrp = tid >> 5;
    const int cnt = d_flagCount;

    for (int base = blockIdx.x * 16; base < cnt; base += gridDim.x * 16) {
        const int nr = min(16, cnt - base);
        for (int i = tid; i < 16 * DIMS; i += 256)
            ((float*)zr)[i] = 0.0f;
        __syncthreads();
        if (tid < nr) sRow[tid] = d_flagList[base + tid];
        __syncthreads();
        for (int i = tid; i < nr * DIMS; i += 256)
            zr[i >> 8][i & 255] = z[(size_t)sRow[i >> 8] * DIMS + (i & 255)];
        __syncthreads();

        float bb[16]; int bi[16];
        #pragma unroll
        for (int r = 0; r < 16; r++) { bb[r] = 3.4e38f; bi[r] = 0x7FFFFFFF; }

        #pragma unroll
        for (int cc = 0; cc < 4; cc++) {
            const int c = tid + cc * 256;
            const float4* cp = (const float4*)(cb + (size_t)c * DIMS);
            #pragma unroll
            for (int pass = 0; pass < 2; pass++) {
                float dot[8];
                #pragma unroll
                for (int r = 0; r < 8; r++) dot[r] = 0.0f;
                for (int q = 0; q < 64; q++) {
                    float4 cv = cp[q];
                    #pragma unroll
                    for (int r = 0; r < 8; r++) {
                        float4 zv = *(const float4*)&zr[pass * 8 + r][q * 4];
                        dot[r] = fmaf(zv.x, cv.x, dot[r]);
                        dot[r] = fmaf(zv.y, cv.y, dot[r]);
                        dot[r] = fmaf(zv.z, cv.z, dot[r]);
                        dot[r] = fmaf(zv.w, cv.w, dot[r]);
                    }
                }
                float cn = __ldg(&d_cnorm[c]);
                #pragma unroll
                for (int r = 0; r < 8; r++) {
                    float cost = fmaf(-2.0f, dot[r], cn);
                    int rr = pass * 8 + r;
                    if (cost < bb[rr] || (cost == bb[rr] && c < bi[rr])) {
                        bb[rr] = cost; bi[rr] = c;
                    }
                }
            }
        }
        #pragma unroll
        for (int off = 16; off > 0; off >>= 1) {
            #pragma unroll
            for (int r = 0; r < 16; r++) {
                float vv = __shfl_xor_sync(0xFFFFFFFFu, bb[r], off);
                int ii = __shfl_xor_sync(0xFFFFFFFFu, bi[r], off);
                if (vv < bb[r] || (vv == bb[r] && ii < bi[r])) { bb[r] = vv; bi[r] = ii; }
            }
        }
        if (lane == 0) {
            #pragma unroll
            for (int r = 0; r < 16; r++) { sRV[r][wrp] = bb[r]; sRI[r][wrp] = bi[r]; }
        }
        __syncthreads();
        if (tid < nr) {
            float bv = 3.4e38f; int bix = 0x7FFFFFFF;
            #pragma unroll
            for (int w = 0; w < 8; w++) {
                float v = sRV[tid][w]; int ix = sRI[tid][w];
                if (v < bv || (v == bv && ix < bix)) { bv = v; bix = ix; }
            }
            int old = d_idx[sRow[tid]];
            sFix[tid] = bix;
            if (bix != old) {
                d_idx[sRow[tid]] = bix;
                atomicAdd(&d_counts[old], -1.0f);
                atomicAdd(&d_counts[bix], 1.0f);
            }
        }
        __syncthreads();
        const float4* cb4 = (const float4*)cb;
        float4* out4 = (float4*)out;
        for (int i = tid; i < nr * 64; i += 256) {
            int r = i >> 6, q = i & 63;
            out4[(size_t)sRow[r] * 64 + q] = cb4[(size_t)sFix[r] * 64 + q];
        }
        __syncthreads();
    }
}

// ---------------------------------------------------------------------------
__global__ void perp_kernel(float* __restrict__ out, int nd, float n) {
    __shared__ float s[KCODES];
    int t = threadIdx.x;
    float e = d_counts[t] / n;
    s[t] = e * logf(e + 1e-10f);
    __syncthreads();
    for (int st = KCODES / 2; st > 0; st >>= 1) {
        if (t < st) s[t] += s[t + st];
        __syncthreads();
    }
    if (t == 0) {
        out[nd] = 0.0f;
        out[nd + 1] = expf(-s[0]);
    }
}

extern "C" void kernel_launch(void* const* d_in, const int* in_sizes, int n_in,
                              void* d_out, int out_size) {
    const float* z = (const float*)d_in[0];
    const float* cb = (const float*)d_in[1];
    float* out = (float*)d_out;

    int nrows = in_sizes[0] / DIMS;  // 65536
    cudaFuncSetAttribute(vq_kernel, cudaFuncAttributeMaxDynamicSharedMemorySize,
                         DSMEM_BYTES);
    prep_kernel<<<128, 256>>>(cb);
    vq_kernel<<<nrows / BM, NTHREADS, DSMEM_BYTES>>>(z, cb, out);
    rescan_kernel<<<256, 256>>>(z, cb, out);
    long nd = (long)nrows * DIMS;
    if ((long)out_size >= nd + 2)
        perp_kernel<<<1, KCODES>>>(out, (int)nd, (float)nrows);
}